// round 12
// baseline (speedup 1.0000x reference)
#include <cuda_runtime.h>
#include <math.h>
#include <stdint.h>

// Problem constants
#define L_SEQ 2048
#define B_SZ  32
#define DIN   128
#define DST   512
#define NB4   4      // batches per cluster

// Scratch (device globals per allocation rules)
__device__ float g_pre[L_SEQ * B_SZ * DST];   // [l][b][h]   128 MB
__device__ float g_hs [L_SEQ * B_SZ * DST];   // [l][b][h]   128 MB
__device__ float g_xT [L_SEQ * B_SZ * DIN];   // [l][b][d]    32 MB

union F4U  { float4 f4; ulonglong2 u2; };
union U64F { unsigned long long u; float2 f; };

__device__ __forceinline__ void ffma2(unsigned long long& acc,
                                      unsigned long long a,
                                      unsigned long long b) {
    asm volatile("fma.rn.f32x2 %0, %1, %2, %0;" : "+l"(acc) : "l"(a), "l"(b));
}

__device__ __forceinline__ uint32_t smem_u32(const void* p) {
    return (uint32_t)__cvta_generic_to_shared(p);
}

// Fast tanh for the recurrent chain: MUFU.EX2-based, ~1e-7 abs error.
__device__ __forceinline__ float ftanh(float x) {
    float e = __expf(2.0f * x);
    return (e - 1.0f) / (e + 1.0f);
}

__device__ __forceinline__ void mbar_wait_cluster(uint32_t addr, uint32_t parity) {
    asm volatile(
        "{\n\t"
        ".reg .pred P;\n\t"
        "WAIT%=:\n\t"
        "mbarrier.try_wait.parity.acquire.cluster.shared::cta.b64 P, [%0], %1, 0x989680;\n\t"
        "@P bra DONE%=;\n\t"
        "bra WAIT%=;\n\t"
        "DONE%=:\n\t"
        "}\n"
        :: "r"(addr), "r"(parity) : "memory");
}

// ---------------------------------------------------------------------------
// Kernel 0: transpose x[b][d][l] -> xT[l][b*128+d].
// ---------------------------------------------------------------------------
__global__ void __launch_bounds__(256) k_xT(const float* __restrict__ x) {
    __shared__ float sm[32 * 33];
    const int l0  = blockIdx.x * 32;
    const int bd0 = blockIdx.y * 32;
    const int t   = threadIdx.x;
    for (int i = t; i < 1024; i += 256) {
        int r = i >> 5, c = i & 31;
        sm[r * 33 + c] = x[(size_t)(bd0 + r) * L_SEQ + l0 + c];
    }
    __syncthreads();
    for (int i = t; i < 1024; i += 256) {
        int r = i >> 5, c = i & 31;
        g_xT[(size_t)(l0 + r) * (B_SZ * DIN) + bd0 + c] = sm[c * 33 + r];
    }
}

// ---------------------------------------------------------------------------
// Kernel 1: pre[l][b][h]. 2 timesteps per block (W staged once).
// ---------------------------------------------------------------------------
#define PRE_SMEM ((128 * 257 + 128 * 36) * 4)

__global__ void __launch_bounds__(512) k_pre(const float* __restrict__ Wih,
                                             const float* __restrict__ bih,
                                             const float* __restrict__ bhh) {
    extern __shared__ float sm[];
    float* w_s = sm;               // [128 d][257]
    float* x_s = sm + 128 * 257;   // [128 d][36]

    const int lbase = blockIdx.x * 2;
    const int h0 = blockIdx.y * 256;
    const int t  = threadIdx.x;

    for (int idx = t; idx < 256 * 128; idx += 512) {
        int d = idx & 127, hh = idx >> 7;
        w_s[d * 257 + hh] = Wih[(size_t)(h0 + hh) * DIN + d];
    }

    const int tx = t & 63;
    const int b0 = (t >> 6) * 4;

    float bias[4];
#pragma unroll
    for (int j = 0; j < 4; j++)
        bias[j] = bih[h0 + tx + 64 * j] + bhh[h0 + tx + 64 * j];

    for (int l2 = 0; l2 < 2; l2++) {
        const int l = lbase + l2;
        __syncthreads();
        for (int idx = t; idx < B_SZ * DIN; idx += 512) {
            int d = idx & 127, b = idx >> 7;
            x_s[d * 36 + b] = g_xT[(size_t)l * (B_SZ * DIN) + b * DIN + d];
        }
        __syncthreads();

        unsigned long long acc[2][4];
#pragma unroll
        for (int m = 0; m < 2; m++)
#pragma unroll
            for (int b = 0; b < 4; b++) acc[m][b] = 0ull;

#pragma unroll 4
        for (int k = 0; k < 128; k++) {
            const float* wr = w_s + k * 257 + tx;
            U64F p0, p1;
            p0.f.x = wr[0];   p0.f.y = wr[64];
            p1.f.x = wr[128]; p1.f.y = wr[192];
            F4U xv; xv.f4 = *(const float4*)(x_s + k * 36 + b0);
            float xs[4] = {xv.f4.x, xv.f4.y, xv.f4.z, xv.f4.w};
#pragma unroll
            for (int b = 0; b < 4; b++) {
                U64F d2; d2.f.x = xs[b]; d2.f.y = xs[b];
                ffma2(acc[0][b], p0.u, d2.u);
                ffma2(acc[1][b], p1.u, d2.u);
            }
        }

#pragma unroll
        for (int b = 0; b < 4; b++) {
            float* pr = g_pre + ((size_t)l * B_SZ + b0 + b) * DST + h0 + tx;
            U64F u0, u1; u0.u = acc[0][b]; u1.u = acc[1][b];
            pr[0]   = u0.f.x + bias[0];
            pr[64]  = u0.f.y + bias[1];
            pr[128] = u1.f.x + bias[2];
            pr[192] = u1.f.y + bias[3];
        }
    }
}

// ---------------------------------------------------------------------------
// Kernel 2: recurrent scan, OWNER-COMPUTES-K-SLICE dataflow.
// 8 clusters x 8 CTAs x 640 threads; 4 batches per cluster.
// CTA rank's K-slice = its OWN 64 h rows (locally produced) -> compute warps
// need NO remote input. Warp w computes partials for dst rows [32w,+32)
// (owner = CTA w>>1) against the local slice, pushes one 128B coalesced
// DSMEM store per batch to the owner's red[], then one remote arrive.
// Owner's tail (1 warp/batch): wait 2 count-8 mbarriers, reduce 8 partials,
// tanh, write g_hs + local hbuf, local named-bar arrive. No h broadcast.
// red[] parity double-buffered (2-step reuse, release/acquire chain-safe);
// named bars alternate by step parity; trailing cluster barrier.
// ---------------------------------------------------------------------------
__global__ void __launch_bounds__(640, 1) __cluster_dims__(8, 1, 1)
k_rnn(const float* __restrict__ Whh) {
    __shared__ float hbuf[2][NB4][64];          // [parity][batch][own rows]
    __shared__ float red[2][NB4][8][64];        // [parity][batch][src][row] 16KB
    __shared__ __align__(8) unsigned long long barr[NB4][2][2]; // [b][slot][half]

    const int t    = threadIdx.x;
    const int warp = t >> 5;
    const int lane = t & 31;
    uint32_t rank;
    asm("mov.u32 %0, %%cluster_ctarank;" : "=r"(rank));
    const int cl = blockIdx.x >> 3;             // cluster id 0..7

    // compute-warp constants + register W (rows = destinations, K = own slice)
    const int peer   = warp >> 1;               // owner CTA of my dst rows
    const int half   = warp & 1;
    const int rowloc = half * 32 + lane;        // row within owner (0..63)
    F4U w[16];
    if (t < 512) {
        const float4* wp =
            (const float4*)(Whh + (size_t)(warp * 32 + lane) * DST + rank * 64);
#pragma unroll
        for (int i = 0; i < 16; i++) w[i].f4 = wp[i];
    }

    // h_{-1} = 0 lives in parity buffer 1
    for (int i = t; i < NB4 * 64; i += 640) (&hbuf[1][0][0])[i] = 0.f;

    uint32_t bar0 = smem_u32(&barr[0][0][0]);
    if (t == 0) {
        for (int i = 0; i < NB4 * 2 * 2; i++)
            asm volatile("mbarrier.init.shared.b64 [%0], %1;"
                         :: "r"(bar0 + 8u * i), "r"(8u) : "memory");
        asm volatile("fence.mbarrier_init.release.cluster;" ::: "memory");
    }
    __syncthreads();
    asm volatile("barrier.cluster.arrive.aligned;" ::: "memory");
    asm volatile("barrier.cluster.wait.aligned;" ::: "memory");

    const uint32_t red0 = smem_u32(&red[0][0][0][0]);

    if (t < 512) {
        // ================= COMPUTE WARPS =================
        uint32_t peer_red, peer_bar;
        asm("mapa.shared::cluster.u32 %0, %1, %2;" : "=r"(peer_red) : "r"(red0), "r"(peer));
        asm("mapa.shared::cluster.u32 %0, %1, %2;" : "=r"(peer_bar) : "r"(bar0), "r"(peer));

        for (int l = 0; l < L_SEQ; l++) {
            const int prev = (l & 1) ^ 1;       // hbuf written by tail at l-1
            const int rbuf = l & 1;
            const int slot = l & 1;

#pragma unroll
            for (int b = 0; b < NB4; b++) {
                if (l > 0)
                    asm volatile("bar.sync %0, 544;"
                                 :: "r"(1 + b * 2 + (l & 1)) : "memory");
                const float4* hp = (const float4*)&hbuf[prev][b][0];
                unsigned long long a0 = 0ull, a1 = 0ull;
#pragma unroll
                for (int i = 0; i < 16; i++) {
                    F4U hv; hv.f4 = hp[i];      // all lanes same addr: broadcast
                    ffma2(a0, hv.u2.x, w[i].u2.x);
                    ffma2(a1, hv.u2.y, w[i].u2.y);
                }
                U64F u0, u1; u0.u = a0; u1.u = a1;
                float partial = u0.f.x + u0.f.y + u1.f.x + u1.f.y;
                // push to owner: 32 lanes = one coalesced 128B DSMEM store
                uint32_t off = (uint32_t)((((rbuf * NB4 + b) * 8 + (int)rank) * 64
                                           + rowloc) * 4);
                asm volatile("st.shared::cluster.f32 [%0], %1;"
                             :: "r"(peer_red + off), "f"(partial) : "memory");
                __syncwarp();
                if (lane == 0) {
                    uint32_t ba = peer_bar + 8u * (uint32_t)((b * 2 + slot) * 2 + half);
                    asm volatile("mbarrier.arrive.release.cluster.shared::cluster.b64 _, [%0];"
                                 :: "r"(ba) : "memory");
                }
            }
        }
    } else {
        // ================= TAIL WARPS (one per batch) =================
        const int tb = warp - 16;               // my batch 0..3
        const int u  = lane;                    // rows 2u, 2u+1
        const size_t oi0 = (size_t)(cl * NB4 + tb) * DST + rank * 64 + 2 * u;

        for (int l = 0; l < L_SEQ; l++) {
            const int slot = l & 1;
            const int rbuf = l & 1;
            const uint32_t wpar = (uint32_t)((l >> 1) & 1);
            float2 pv = *(const float2*)(g_pre + (size_t)l * (B_SZ * DST) + oi0);

            // wait for both half-barriers (8 source CTAs each)
            mbar_wait_cluster(bar0 + 8u * (uint32_t)((tb * 2 + slot) * 2 + 0), wpar);
            mbar_wait_cluster(bar0 + 8u * (uint32_t)((tb * 2 + slot) * 2 + 1), wpar);

            float s0 = pv.x, s1 = pv.y;
#pragma unroll
            for (int s = 0; s < 8; s++) {
                float2 v = *(const float2*)&red[rbuf][tb][s][2 * u];
                s0 += v.x; s1 += v.y;
            }
            U64F hv2; hv2.f.x = ftanh(s0); hv2.f.y = ftanh(s1);
            *(float2*)(g_hs + (size_t)l * (B_SZ * DST) + oi0) = hv2.f;
            *(float2*)&hbuf[slot][tb][2 * u] = hv2.f;   // local only!

            if (l < L_SEQ - 1)
                asm volatile("bar.arrive %0, 544;"
                             :: "r"(1 + tb * 2 + ((l + 1) & 1)) : "memory");
        }
    }

    // No CTA may exit while peers could still touch its smem.
    asm volatile("barrier.cluster.arrive.aligned;" ::: "memory");
    asm volatile("barrier.cluster.wait.aligned;" ::: "memory");
}

// ---------------------------------------------------------------------------
// Kernel 3: y[lb][o] = tanh(b_fc[o] + sum_k hs[lb][k] * W_fc[o][k])
// ---------------------------------------------------------------------------
#define OUT_SMEM ((128 * 132 + 128 * 68) * 4)

__global__ void __launch_bounds__(512) k_out(const float* __restrict__ Wfc,
                                             const float* __restrict__ bfc,
                                             float* __restrict__ y) {
    extern __shared__ float sm[];
    float* w_s = sm;               // [128 kk][132]
    float* a_s = sm + 128 * 132;   // [128 kk][68]

    const int t = threadIdx.x;
    const size_t base = (size_t)blockIdx.x * 64;
    const int tx  = t & 31;
    const int lb0 = (t >> 5) * 4;

    unsigned long long acc[2][4];
#pragma unroll
    for (int m = 0; m < 2; m++)
#pragma unroll
        for (int b = 0; b < 4; b++) acc[m][b] = 0ull;

    for (int kc = 0; kc < 4; kc++) {
        __syncthreads();
        for (int idx = t; idx < 128 * 128; idx += 512) {
            int kk = idx & 127, o = idx >> 7;
            w_s[kk * 132 + o] = Wfc[(size_t)o * DST + kc * 128 + kk];
        }
        for (int idx = t; idx < 64 * 128; idx += 512) {
            int kk = idx & 127, row = idx >> 7;
            a_s[kk * 68 + row] = g_hs[(base + row) * DST + kc * 128 + kk];
        }
        __syncthreads();

#pragma unroll 4
        for (int k = 0; k < 128; k++) {
            const float* wr = w_s + k * 132 + tx;
            U64F p0, p1;
            p0.f.x = wr[0];  p0.f.y = wr[32];
            p1.f.x = wr[64]; p1.f.y = wr[96];
            F4U av; av.f4 = *(const float4*)(a_s + k * 68 + lb0);
            float as4[4] = {av.f4.x, av.f4.y, av.f4.z, av.f4.w};
#pragma unroll
            for (int b = 0; b < 4; b++) {
                U64F d2; d2.f.x = as4[b]; d2.f.y = as4[b];
                ffma2(acc[0][b], p0.u, d2.u);
                ffma2(acc[1][b], p1.u, d2.u);
            }
        }
    }

    float bias[4];
#pragma unroll
    for (int j = 0; j < 4; j++) bias[j] = bfc[tx + 32 * j];

#pragma unroll
    for (int b = 0; b < 4; b++) {
        float* yp = y + (base + lb0 + b) * DIN + tx;
        U64F u0, u1; u0.u = acc[0][b]; u1.u = acc[1][b];
        yp[0]  = tanhf(u0.f.x + bias[0]);
        yp[32] = tanhf(u0.f.y + bias[1]);
        yp[64] = tanhf(u1.f.x + bias[2]);
        yp[96] = tanhf(u1.f.y + bias[3]);
    }
}

// ---------------------------------------------------------------------------
extern "C" void kernel_launch(void* const* d_in, const int* in_sizes, int n_in,
                              void* d_out, int out_size) {
    const float* x   = (const float*)d_in[0];
    const float* Wih = (const float*)d_in[1];
    const float* Whh = (const float*)d_in[2];
    const float* bih = (const float*)d_in[3];
    const float* bhh = (const float*)d_in[4];
    const float* Wfc = (const float*)d_in[5];
    const float* bfc = (const float*)d_in[6];
    float* y = (float*)d_out;

    cudaFuncSetAttribute(k_pre, cudaFuncAttributeMaxDynamicSharedMemorySize, PRE_SMEM);
    cudaFuncSetAttribute(k_out, cudaFuncAttributeMaxDynamicSharedMemorySize, OUT_SMEM);

    k_xT<<<dim3(L_SEQ / 32, (B_SZ * DIN) / 32), 256>>>(x);
    k_pre<<<dim3(L_SEQ / 2, 2), 512, PRE_SMEM>>>(Wih, bih, bhh);
    k_rnn<<<64, 640>>>(Whh);
    k_out<<<(L_SEQ * B_SZ) / 64, 512, OUT_SMEM>>>(Wfc, bfc, y);
}

// round 15
// speedup vs baseline: 1.6636x; 1.6636x over previous
#include <cuda_runtime.h>
#include <math.h>
#include <stdint.h>

// Problem constants
#define L_SEQ 2048
#define B_SZ  32
#define DIN   128
#define DST   512
#define NB4   4      // batches per rnn cluster

// Scratch (device globals per allocation rules)
__device__ float g_pre[L_SEQ * B_SZ * DST];   // [l][b][h]   128 MB
__device__ float g_hs [L_SEQ * B_SZ * DST];   // [l][b][h]   128 MB
__device__ float g_xT [L_SEQ * B_SZ * DIN];   // [l][b][d]    32 MB
__device__ unsigned g_done[L_SEQ];            // h[l] published count (target 256)

union F4U  { float4 f4; ulonglong2 u2; };
union U64F { unsigned long long u; float2 f; };

__device__ __forceinline__ void ffma2(unsigned long long& acc,
                                      unsigned long long a,
                                      unsigned long long b) {
    asm volatile("fma.rn.f32x2 %0, %1, %2, %0;" : "+l"(acc) : "l"(a), "l"(b));
}

__device__ __forceinline__ uint32_t smem_u32(const void* p) {
    return (uint32_t)__cvta_generic_to_shared(p);
}

__device__ __forceinline__ float ftanh(float x) {
    float e = __expf(2.0f * x);
    return (e - 1.0f) / (e + 1.0f);
}

__device__ __forceinline__ void mbar_wait_cluster(uint32_t addr, uint32_t parity) {
    asm volatile(
        "{\n\t"
        ".reg .pred P;\n\t"
        "WAIT%=:\n\t"
        "mbarrier.try_wait.parity.acquire.cluster.shared::cta.b64 P, [%0], %1, 0x989680;\n\t"
        "@P bra DONE%=;\n\t"
        "bra WAIT%=;\n\t"
        "DONE%=:\n\t"
        "}\n"
        :: "r"(addr), "r"(parity) : "memory");
}

__device__ __forceinline__ unsigned ld_acq_gpu(const unsigned* p) {
    unsigned v;
    asm volatile("ld.acquire.gpu.u32 %0, [%1];" : "=r"(v) : "l"(p) : "memory");
    return v;
}

__device__ __forceinline__ void red_rel_add(unsigned* p, unsigned v) {
    asm volatile("red.release.gpu.add.u32 [%0], %1;" :: "l"(p), "r"(v) : "memory");
}

// ---------------------------------------------------------------------------
// Kernel 0: transpose x[b][d][l] -> xT[l][b*128+d].
// ---------------------------------------------------------------------------
__global__ void __launch_bounds__(256) k_xT(const float* __restrict__ x) {
    __shared__ float sm[32 * 33];
    const int l0  = blockIdx.x * 32;
    const int bd0 = blockIdx.y * 32;
    const int t   = threadIdx.x;
    for (int i = t; i < 1024; i += 256) {
        int r = i >> 5, c = i & 31;
        sm[r * 33 + c] = x[(size_t)(bd0 + r) * L_SEQ + l0 + c];
    }
    __syncthreads();
    for (int i = t; i < 1024; i += 256) {
        int r = i >> 5, c = i & 31;
        g_xT[(size_t)(l0 + r) * (B_SZ * DIN) + bd0 + c] = sm[c * 33 + r];
    }
}

// ---------------------------------------------------------------------------
// Kernel 1: pre[l][b][h]. 128 persistent-ish CTAs; each stages its W_ih half
// ONCE and sweeps 32 timesteps (l = bid/2 + 64*i) — W re-read eliminated.
// ---------------------------------------------------------------------------
#define PRE_SMEM ((128 * 257 + 128 * 36) * 4)

__global__ void __launch_bounds__(512) k_pre(const float* __restrict__ Wih,
                                             const float* __restrict__ bih,
                                             const float* __restrict__ bhh) {
    extern __shared__ float sm[];
    float* w_s = sm;               // [128 d][257]
    float* x_s = sm + 128 * 257;   // [128 d][36]

    const int hb    = blockIdx.x & 1;
    const int h0    = hb * 256;
    const int lbase = blockIdx.x >> 1;   // 0..63
    const int t     = threadIdx.x;

    for (int idx = t; idx < 256 * 128; idx += 512) {
        int d = idx & 127, hh = idx >> 7;
        w_s[d * 257 + hh] = Wih[(size_t)(h0 + hh) * DIN + d];
    }

    const int tx = t & 63;
    const int b0 = (t >> 6) * 4;

    float bias[4];
#pragma unroll
    for (int j = 0; j < 4; j++)
        bias[j] = bih[h0 + tx + 64 * j] + bhh[h0 + tx + 64 * j];
    __syncthreads();

    for (int i = 0; i < 32; i++) {
        const int l = lbase + 64 * i;
        for (int idx = t; idx < B_SZ * DIN; idx += 512) {
            int d = idx & 127, b = idx >> 7;
            x_s[d * 36 + b] = g_xT[(size_t)l * (B_SZ * DIN) + b * DIN + d];
        }
        __syncthreads();

        unsigned long long acc[2][4];
#pragma unroll
        for (int m = 0; m < 2; m++)
#pragma unroll
            for (int b = 0; b < 4; b++) acc[m][b] = 0ull;

#pragma unroll 4
        for (int k = 0; k < 128; k++) {
            const float* wr = w_s + k * 257 + tx;
            U64F p0, p1;
            p0.f.x = wr[0];   p0.f.y = wr[64];
            p1.f.x = wr[128]; p1.f.y = wr[192];
            F4U xv; xv.f4 = *(const float4*)(x_s + k * 36 + b0);
            float xs[4] = {xv.f4.x, xv.f4.y, xv.f4.z, xv.f4.w};
#pragma unroll
            for (int b = 0; b < 4; b++) {
                U64F d2; d2.f.x = xs[b]; d2.f.y = xs[b];
                ffma2(acc[0][b], p0.u, d2.u);
                ffma2(acc[1][b], p1.u, d2.u);
            }
        }

#pragma unroll
        for (int b = 0; b < 4; b++) {
            float* pr = g_pre + ((size_t)l * B_SZ + b0 + b) * DST + h0 + tx;
            U64F u0, u1; u0.u = acc[0][b]; u1.u = acc[1][b];
            pr[0]   = u0.f.x + bias[0];
            pr[64]  = u0.f.y + bias[1];
            pr[128] = u1.f.x + bias[2];
            pr[192] = u1.f.y + bias[3];
        }
        __syncthreads();     // x_s reusable next iteration
    }
}

// ---------------------------------------------------------------------------
// Fused kernel: 128 CTAs (16 clusters of 8), 640 threads.
//   CTAs 0-63: R10-champion recurrent scan (g_pre already complete; no gating)
//              + one done-counter publish per tail warp per step.
//   CTAs 64-127: k_out workers, gated on done[l] — they depend ONLY on rnn,
//              which never depends on them: acyclic, so partial cluster
//              residency degrades to sequential execution, never deadlock.
// ---------------------------------------------------------------------------
#define OUT_SMEM ((128 * 132 + 128 * 68) * 4)

__global__ void __launch_bounds__(640, 1) __cluster_dims__(8, 1, 1)
k_fused(const float* __restrict__ Whh,
        const float* __restrict__ Wfc,
        const float* __restrict__ bfc,
        float* __restrict__ y) {
    extern __shared__ float dsm[];
    __shared__ float hbuf[2][NB4 * DST];     // rnn: 16 KB
    __shared__ float red[2][NB4][64][9];     // rnn: 18 KB
    __shared__ __align__(8) unsigned long long barr[NB4][2][8];

    const int t    = threadIdx.x;
    const int warp = t >> 5;
    const int lane = t & 31;

    if (blockIdx.x < 64) {
        // ===================== RNN (R10 champion) =====================
        uint32_t rank;
        asm("mov.u32 %0, %%cluster_ctarank;" : "=r"(rank));
        const int cl = blockIdx.x >> 3;

        const int rg  = warp & 1;
        const int kw  = warp >> 1;
        const int row = rg * 32 + lane;
        const int ks  = kw * 64;
        F4U w[16];
        if (t < 512) {
            const float4* wp = (const float4*)(Whh + (size_t)(rank * 64 + row) * DST + ks);
#pragma unroll
            for (int i = 0; i < 16; i++) w[i].f4 = wp[i];
        }

        for (int i = t; i < NB4 * DST; i += 640) hbuf[1][i] = 0.f;

        uint32_t bar0 = smem_u32(&barr[0][0][0]);
        if (t == 0) {
            for (int i = 0; i < NB4 * 2 * 8; i++)
                asm volatile("mbarrier.init.shared.b64 [%0], %1;"
                             :: "r"(bar0 + 8u * i), "r"(1u) : "memory");
            asm volatile("fence.mbarrier_init.release.cluster;" ::: "memory");
        }
        __syncthreads();
        asm volatile("barrier.cluster.arrive.aligned;" ::: "memory");
        asm volatile("barrier.cluster.wait.aligned;" ::: "memory");

        const uint32_t hbase = smem_u32(&hbuf[0][0]);
        uint32_t peer_h[8];
#pragma unroll
        for (int p = 0; p < 8; p++)
            asm("mapa.shared::cluster.u32 %0, %1, %2;" : "=r"(peer_h[p]) : "r"(hbase), "r"(p));

        if (t < 512) {
            // ---- compute warps ----
            for (int l = 0; l < L_SEQ; l++) {
                const int prev = (l & 1) ^ 1;
                const int rbuf = l & 1;
                const uint32_t wslot = (uint32_t)((l - 1) & 1);
                const uint32_t wpar  = (uint32_t)(((l - 1) >> 1) & 1);
                const float* hbp = hbuf[prev];
                const uint32_t srcoff = 8u * (wslot * 8u + (uint32_t)kw);

#pragma unroll
                for (int b = 0; b < NB4; b++) {
                    if (l > 0)
                        mbar_wait_cluster(bar0 + (uint32_t)(b * 128) + srcoff, wpar);
                    const float4* hp = (const float4*)(hbp + b * DST + ks);
                    unsigned long long a0 = 0ull, a1 = 0ull;
#pragma unroll
                    for (int i = 0; i < 16; i++) {
                        F4U hv; hv.f4 = hp[i];
                        ffma2(a0, hv.u2.x, w[i].u2.x);
                        ffma2(a1, hv.u2.y, w[i].u2.y);
                    }
                    U64F u0, u1; u0.u = a0; u1.u = a1;
                    red[rbuf][b][row][kw] = u0.f.x + u0.f.y + u1.f.x + u1.f.y;
                    asm volatile("bar.arrive %0, 544;"
                                 :: "r"(1 + b * 2 + (l & 1)) : "memory");
                }
            }
        } else {
            // ---- tail warps (one per batch) ----
            const int tb = warp - 16;
            const int u  = lane;
            const size_t oi0 = (size_t)(cl * NB4 + tb) * DST + rank * 64 + 2 * u;
            const uint32_t po0 = (uint32_t)((tb * DST + (int)rank * 64 + 2 * u) * 4);

            for (int l = 0; l < L_SEQ; l++) {
                const int cur  = l & 1;
                const int rbuf = l & 1;
                float2 pv = *(const float2*)(g_pre + (size_t)l * (B_SZ * DST) + oi0);

                asm volatile("bar.sync %0, 544;"
                             :: "r"(1 + tb * 2 + (l & 1)) : "memory");

                float s0 = pv.x, s1 = pv.y;
#pragma unroll
                for (int k2 = 0; k2 < 8; k2++) {
                    s0 += red[rbuf][tb][2 * u][k2];
                    s1 += red[rbuf][tb][2 * u + 1][k2];
                }
                U64F hv2; hv2.f.x = ftanh(s0); hv2.f.y = ftanh(s1);
                *(float2*)(g_hs + (size_t)l * (B_SZ * DST) + oi0) = hv2.f;

                if (l < L_SEQ - 1) {
                    uint32_t off0 = (uint32_t)(cur * NB4 * DST * 4) + po0;
#pragma unroll
                    for (int p = 0; p < 8; p++)
                        asm volatile("st.shared::cluster.u64 [%0], %1;"
                                     :: "r"(peer_h[p] + off0), "l"(hv2.u) : "memory");
                }
                __syncwarp();   // order pushes + g_hs stores within the warp
                if (l < L_SEQ - 1 && u < 8) {
                    uint32_t local = bar0 + (uint32_t)(tb * 128)
                                   + 8u * ((uint32_t)cur * 8u + rank);
                    uint32_t ra;
                    asm("mapa.shared::cluster.u32 %0, %1, %2;"
                        : "=r"(ra) : "r"(local), "r"(u));
                    asm volatile("mbarrier.arrive.release.cluster.shared::cluster.b64 _, [%0];"
                                 :: "r"(ra) : "memory");
                }
                // publish h[l] for k_out workers (off the recurrence chain)
                if (lane == 0) red_rel_add(g_done + l, 1u);
            }
        }
    } else {
        // ===================== K_OUT WORKERS =====================
        float* w2 = dsm;                  // [128 kk][132]
        float* a2 = dsm + 128 * 132;      // [128 kk][68]
        const int j   = blockIdx.x - 64;  // worker id 0..63
        const int tx  = t & 31;
        const int lb0 = (t >> 5) * 4;     // valid only for t<512

        for (int i = 0; i < 16; i++) {
            const int blk = j + 64 * i;
            const size_t base = (size_t)blk * 64;

            if (t == 0) {
                const unsigned* dp = g_done + (blk * 2 + 1);
                while (ld_acq_gpu(dp) < 256u) __nanosleep(500);
            }
            __syncthreads();

            unsigned long long acc[2][4];
#pragma unroll
            for (int m = 0; m < 2; m++)
#pragma unroll
                for (int b = 0; b < 4; b++) acc[m][b] = 0ull;

            for (int kc = 0; kc < 4; kc++) {
                __syncthreads();
                for (int idx = t; idx < 128 * 128; idx += 640) {
                    int kk = idx & 127, o = idx >> 7;
                    w2[kk * 132 + o] = Wfc[(size_t)o * DST + kc * 128 + kk];
                }
                for (int idx = t; idx < 64 * 128; idx += 640) {
                    int kk = idx & 127, rr = idx >> 7;
                    a2[kk * 68 + rr] = g_hs[(base + rr) * DST + kc * 128 + kk];
                }
                __syncthreads();

                if (t < 512) {
#pragma unroll 4
                    for (int k = 0; k < 128; k++) {
                        const float* wr = w2 + k * 132 + tx;
                        U64F p0, p1;
                        p0.f.x = wr[0];  p0.f.y = wr[32];
                        p1.f.x = wr[64]; p1.f.y = wr[96];
                        F4U av; av.f4 = *(const float4*)(a2 + k * 68 + lb0);
                        float as4[4] = {av.f4.x, av.f4.y, av.f4.z, av.f4.w};
#pragma unroll
                        for (int b = 0; b < 4; b++) {
                            U64F d2; d2.f.x = as4[b]; d2.f.y = as4[b];
                            ffma2(acc[0][b], p0.u, d2.u);
                            ffma2(acc[1][b], p1.u, d2.u);
                        }
                    }
                }
            }

            if (t < 512) {
                float bias[4];
#pragma unroll
                for (int q = 0; q < 4; q++) bias[q] = bfc[tx + 32 * q];
#pragma unroll
                for (int b = 0; b < 4; b++) {
                    float* yp = y + (base + lb0 + b) * DIN + tx;
                    U64F u0, u1; u0.u = acc[0][b]; u1.u = acc[1][b];
                    yp[0]  = tanhf(u0.f.x + bias[0]);
                    yp[32] = tanhf(u0.f.y + bias[1]);
                    yp[64] = tanhf(u1.f.x + bias[2]);
                    yp[96] = tanhf(u1.f.y + bias[3]);
                }
            }
            __syncthreads();   // before next iteration reuses smem
        }
    }

    // Per-cluster exit barrier (rnn clusters: peers may touch smem).
    asm volatile("barrier.cluster.arrive.aligned;" ::: "memory");
    asm volatile("barrier.cluster.wait.aligned;" ::: "memory");
}

// ---------------------------------------------------------------------------
extern "C" void kernel_launch(void* const* d_in, const int* in_sizes, int n_in,
                              void* d_out, int out_size) {
    const float* x   = (const float*)d_in[0];
    const float* Wih = (const float*)d_in[1];
    const float* Whh = (const float*)d_in[2];
    const float* bih = (const float*)d_in[3];
    const float* bhh = (const float*)d_in[4];
    const float* Wfc = (const float*)d_in[5];
    const float* bfc = (const float*)d_in[6];
    float* y = (float*)d_out;

    cudaFuncSetAttribute(k_pre, cudaFuncAttributeMaxDynamicSharedMemorySize, PRE_SMEM);
    cudaFuncSetAttribute(k_fused, cudaFuncAttributeMaxDynamicSharedMemorySize, OUT_SMEM);

    void* fl = nullptr;
    cudaGetSymbolAddress(&fl, g_done);
    cudaMemsetAsync(fl, 0, L_SEQ * sizeof(unsigned), 0);

    k_xT<<<dim3(L_SEQ / 32, (B_SZ * DIN) / 32), 256>>>(x);
    k_pre<<<128, 512, PRE_SMEM>>>(Wih, bih, bhh);
    k_fused<<<128, 640, OUT_SMEM>>>(Whh, Wfc, bfc, y);
}

// round 16
// speedup vs baseline: 2.1005x; 1.2626x over previous
#include <cuda_runtime.h>
#include <math.h>
#include <stdint.h>

// Problem constants
#define L_SEQ 2048
#define B_SZ  32
#define DIN   128
#define DST   512
#define NB4   4      // batches per rnn cluster

// Scratch (device globals per allocation rules)
__device__ float g_pre[L_SEQ * B_SZ * DST];   // [l][b][h]   128 MB
__device__ float g_hs [L_SEQ * B_SZ * DST];   // [l][b][h]   128 MB
__device__ float g_xT [L_SEQ * B_SZ * DIN];   // [l][b][d]    32 MB

union F4U  { float4 f4; ulonglong2 u2; };
union U64F { unsigned long long u; float2 f; };

__device__ __forceinline__ void ffma2(unsigned long long& acc,
                                      unsigned long long a,
                                      unsigned long long b) {
    asm volatile("fma.rn.f32x2 %0, %1, %2, %0;" : "+l"(acc) : "l"(a), "l"(b));
}

__device__ __forceinline__ uint32_t smem_u32(const void* p) {
    return (uint32_t)__cvta_generic_to_shared(p);
}

// Fast tanh for the recurrent chain: MUFU.EX2-based, ~1e-7 abs error.
__device__ __forceinline__ float ftanh(float x) {
    float e = __expf(2.0f * x);
    return (e - 1.0f) / (e + 1.0f);
}

__device__ __forceinline__ void mbar_wait_cluster(uint32_t addr, uint32_t parity) {
    asm volatile(
        "{\n\t"
        ".reg .pred P;\n\t"
        "WAIT%=:\n\t"
        "mbarrier.try_wait.parity.acquire.cluster.shared::cta.b64 P, [%0], %1, 0x989680;\n\t"
        "@P bra DONE%=;\n\t"
        "bra WAIT%=;\n\t"
        "DONE%=:\n\t"
        "}\n"
        :: "r"(addr), "r"(parity) : "memory");
}

// ---------------------------------------------------------------------------
// Kernel 0: transpose x[b][d][l] -> xT[l][b*128+d].
// ---------------------------------------------------------------------------
__global__ void __launch_bounds__(256) k_xT(const float* __restrict__ x) {
    __shared__ float sm[32 * 33];
    const int l0  = blockIdx.x * 32;
    const int bd0 = blockIdx.y * 32;
    const int t   = threadIdx.x;
    for (int i = t; i < 1024; i += 256) {
        int r = i >> 5, c = i & 31;
        sm[r * 33 + c] = x[(size_t)(bd0 + r) * L_SEQ + l0 + c];
    }
    __syncthreads();
    for (int i = t; i < 1024; i += 256) {
        int r = i >> 5, c = i & 31;
        g_xT[(size_t)(l0 + r) * (B_SZ * DIN) + bd0 + c] = sm[c * 33 + r];
    }
}

// ---------------------------------------------------------------------------
// Kernel 1: pre[l][b][h]. 128 CTAs; each stages its W_ih half ONCE and
// sweeps 32 timesteps (l = bid/2 + 64*i) — W re-read eliminated (R15-proven).
// ---------------------------------------------------------------------------
#define PRE_SMEM ((128 * 257 + 128 * 36) * 4)

__global__ void __launch_bounds__(512) k_pre(const float* __restrict__ Wih,
                                             const float* __restrict__ bih,
                                             const float* __restrict__ bhh) {
    extern __shared__ float sm[];
    float* w_s = sm;               // [128 d][257]
    float* x_s = sm + 128 * 257;   // [128 d][36]

    const int hb    = blockIdx.x & 1;
    const int h0    = hb * 256;
    const int lbase = blockIdx.x >> 1;   // 0..63
    const int t     = threadIdx.x;

    for (int idx = t; idx < 256 * 128; idx += 512) {
        int d = idx & 127, hh = idx >> 7;
        w_s[d * 257 + hh] = Wih[(size_t)(h0 + hh) * DIN + d];
    }

    const int tx = t & 63;
    const int b0 = (t >> 6) * 4;

    float bias[4];
#pragma unroll
    for (int j = 0; j < 4; j++)
        bias[j] = bih[h0 + tx + 64 * j] + bhh[h0 + tx + 64 * j];
    __syncthreads();

    for (int i = 0; i < 32; i++) {
        const int l = lbase + 64 * i;
        for (int idx = t; idx < B_SZ * DIN; idx += 512) {
            int d = idx & 127, b = idx >> 7;
            x_s[d * 36 + b] = g_xT[(size_t)l * (B_SZ * DIN) + b * DIN + d];
        }
        __syncthreads();

        unsigned long long acc[2][4];
#pragma unroll
        for (int m = 0; m < 2; m++)
#pragma unroll
            for (int b = 0; b < 4; b++) acc[m][b] = 0ull;

#pragma unroll 4
        for (int k = 0; k < 128; k++) {
            const float* wr = w_s + k * 257 + tx;
            U64F p0, p1;
            p0.f.x = wr[0];   p0.f.y = wr[64];
            p1.f.x = wr[128]; p1.f.y = wr[192];
            F4U xv; xv.f4 = *(const float4*)(x_s + k * 36 + b0);
            float xs[4] = {xv.f4.x, xv.f4.y, xv.f4.z, xv.f4.w};
#pragma unroll
            for (int b = 0; b < 4; b++) {
                U64F d2; d2.f.x = xs[b]; d2.f.y = xs[b];
                ffma2(acc[0][b], p0.u, d2.u);
                ffma2(acc[1][b], p1.u, d2.u);
            }
        }

#pragma unroll
        for (int b = 0; b < 4; b++) {
            float* pr = g_pre + ((size_t)l * B_SZ + b0 + b) * DST + h0 + tx;
            U64F u0, u1; u0.u = acc[0][b]; u1.u = acc[1][b];
            pr[0]   = u0.f.x + bias[0];
            pr[64]  = u0.f.y + bias[1];
            pr[128] = u1.f.x + bias[2];
            pr[192] = u1.f.y + bias[3];
        }
        __syncthreads();     // x_s reusable next iteration
    }
}

// ---------------------------------------------------------------------------
// Kernel 2: recurrent scan — R10 CHAMPION, byte-for-byte.
// 8 clusters x 8 CTAs x 640 threads; 4 batches = depth-4 pipeline.
// Per-source count-1 mbarriers; TRYWAIT HW-sleep; red[] parity double-buffer;
// phase named-bars alternate by step parity; last step no push; trailing
// cluster barrier.
// ---------------------------------------------------------------------------
__global__ void __launch_bounds__(640, 1) __cluster_dims__(8, 1, 1)
k_rnn(const float* __restrict__ Whh) {
    __shared__ float hbuf[2][NB4 * DST];     // 16 KB exchange buffers
    __shared__ float red[2][NB4][64][9];     // 18 KB partials, step-parity buffered
    __shared__ __align__(8) unsigned long long barr[NB4][2][8]; // [b][slot][src]

    const int t    = threadIdx.x;
    const int warp = t >> 5;
    const int lane = t & 31;
    uint32_t rank;
    asm("mov.u32 %0, %%cluster_ctarank;" : "=r"(rank));
    const int cl = blockIdx.x >> 3;          // cluster id 0..7

    // compute-warp constants + register W
    const int rg  = warp & 1;
    const int kw  = warp >> 1;               // K slice / source CTA 0..7
    const int row = rg * 32 + lane;          // local row 0..63
    const int ks  = kw * 64;
    F4U w[16];
    if (t < 512) {
        const float4* wp = (const float4*)(Whh + (size_t)(rank * 64 + row) * DST + ks);
#pragma unroll
        for (int i = 0; i < 16; i++) w[i].f4 = wp[i];
    }

    // h_{-1} = 0 lives in parity buffer 1
    for (int i = t; i < NB4 * DST; i += 640) hbuf[1][i] = 0.f;

    uint32_t bar0 = smem_u32(&barr[0][0][0]);
    if (t == 0) {
        for (int i = 0; i < NB4 * 2 * 8; i++)
            asm volatile("mbarrier.init.shared.b64 [%0], %1;"
                         :: "r"(bar0 + 8u * i), "r"(1u) : "memory");
        asm volatile("fence.mbarrier_init.release.cluster;" ::: "memory");
    }
    __syncthreads();
    asm volatile("barrier.cluster.arrive.aligned;" ::: "memory");
    asm volatile("barrier.cluster.wait.aligned;" ::: "memory");

    const uint32_t hbase = smem_u32(&hbuf[0][0]);
    uint32_t peer_h[8];
#pragma unroll
    for (int p = 0; p < 8; p++)
        asm("mapa.shared::cluster.u32 %0, %1, %2;" : "=r"(peer_h[p]) : "r"(hbase), "r"(p));

    if (t < 512) {
        // ================= COMPUTE WARPS =================
        for (int l = 0; l < L_SEQ; l++) {
            const int prev = (l & 1) ^ 1;
            const int rbuf = l & 1;
            const uint32_t wslot = (uint32_t)((l - 1) & 1);
            const uint32_t wpar  = (uint32_t)(((l - 1) >> 1) & 1);
            const float* hbp = hbuf[prev];
            const uint32_t srcoff = 8u * (wslot * 8u + (uint32_t)kw);

#pragma unroll
            for (int b = 0; b < NB4; b++) {
                if (l > 0)
                    mbar_wait_cluster(bar0 + (uint32_t)(b * 128) + srcoff, wpar);
                const float4* hp = (const float4*)(hbp + b * DST + ks);
                unsigned long long a0 = 0ull, a1 = 0ull;
#pragma unroll
                for (int i = 0; i < 16; i++) {
                    F4U hv; hv.f4 = hp[i];      // broadcast LDS
                    ffma2(a0, hv.u2.x, w[i].u2.x);
                    ffma2(a1, hv.u2.y, w[i].u2.y);
                }
                U64F u0, u1; u0.u = a0; u1.u = a1;
                red[rbuf][b][row][kw] = u0.f.x + u0.f.y + u1.f.x + u1.f.y;
                asm volatile("bar.arrive %0, 544;"
                             :: "r"(1 + b * 2 + (l & 1)) : "memory");
            }
        }
    } else {
        // ================= TAIL WARPS (one per batch) =================
        const int tb = warp - 16;               // my batch 0..3
        const int u  = lane;                    // rows 2u, 2u+1 (contiguous)
        const size_t oi0 = (size_t)(cl * NB4 + tb) * DST + rank * 64 + 2 * u;
        const uint32_t po0 = (uint32_t)((tb * DST + (int)rank * 64 + 2 * u) * 4);

        for (int l = 0; l < L_SEQ; l++) {
            const int cur  = l & 1;
            const int rbuf = l & 1;
            float2 pv = *(const float2*)(g_pre + (size_t)l * (B_SZ * DST) + oi0);

            asm volatile("bar.sync %0, 544;"
                         :: "r"(1 + tb * 2 + (l & 1)) : "memory");

            float s0 = pv.x, s1 = pv.y;
#pragma unroll
            for (int k2 = 0; k2 < 8; k2++) {
                s0 += red[rbuf][tb][2 * u][k2];
                s1 += red[rbuf][tb][2 * u + 1][k2];
            }
            U64F hv2; hv2.f.x = ftanh(s0); hv2.f.y = ftanh(s1);
            *(float2*)(g_hs + (size_t)l * (B_SZ * DST) + oi0) = hv2.f;

            if (l < L_SEQ - 1) {
                uint32_t off0 = (uint32_t)(cur * NB4 * DST * 4) + po0;
#pragma unroll
                for (int p = 0; p < 8; p++)
                    asm volatile("st.shared::cluster.u64 [%0], %1;"
                                 :: "r"(peer_h[p] + off0), "l"(hv2.u) : "memory");
                __syncwarp();   // order this warp's pushes before the arrives
                if (u < 8) {
                    uint32_t local = bar0 + (uint32_t)(tb * 128)
                                   + 8u * ((uint32_t)cur * 8u + rank);
                    uint32_t ra;
                    asm("mapa.shared::cluster.u32 %0, %1, %2;"
                        : "=r"(ra) : "r"(local), "r"(u));
                    asm volatile("mbarrier.arrive.release.cluster.shared::cluster.b64 _, [%0];"
                                 :: "r"(ra) : "memory");
                }
            }
        }
    }

    // No CTA may exit while peers could still touch its smem.
    asm volatile("barrier.cluster.arrive.aligned;" ::: "memory");
    asm volatile("barrier.cluster.wait.aligned;" ::: "memory");
}

// ---------------------------------------------------------------------------
// Kernel 3: y[lb][o] = tanh(b_fc[o] + sum_k hs[lb][k] * W_fc[o][k])
// ---------------------------------------------------------------------------
#define OUT_SMEM ((128 * 132 + 128 * 68) * 4)

__global__ void __launch_bounds__(512) k_out(const float* __restrict__ Wfc,
                                             const float* __restrict__ bfc,
                                             float* __restrict__ y) {
    extern __shared__ float sm[];
    float* w_s = sm;               // [128 kk][132]
    float* a_s = sm + 128 * 132;   // [128 kk][68]

    const int t = threadIdx.x;
    const size_t base = (size_t)blockIdx.x * 64;
    const int tx  = t & 31;
    const int lb0 = (t >> 5) * 4;

    unsigned long long acc[2][4];
#pragma unroll
    for (int m = 0; m < 2; m++)
#pragma unroll
        for (int b = 0; b < 4; b++) acc[m][b] = 0ull;

    for (int kc = 0; kc < 4; kc++) {
        __syncthreads();
        for (int idx = t; idx < 128 * 128; idx += 512) {
            int kk = idx & 127, o = idx >> 7;
            w_s[kk * 132 + o] = Wfc[(size_t)o * DST + kc * 128 + kk];
        }
        for (int idx = t; idx < 64 * 128; idx += 512) {
            int kk = idx & 127, row = idx >> 7;
            a_s[kk * 68 + row] = g_hs[(base + row) * DST + kc * 128 + kk];
        }
        __syncthreads();

#pragma unroll 4
        for (int k = 0; k < 128; k++) {
            const float* wr = w_s + k * 132 + tx;
            U64F p0, p1;
            p0.f.x = wr[0];  p0.f.y = wr[32];
            p1.f.x = wr[64]; p1.f.y = wr[96];
            F4U av; av.f4 = *(const float4*)(a_s + k * 68 + lb0);
            float as4[4] = {av.f4.x, av.f4.y, av.f4.z, av.f4.w};
#pragma unroll
            for (int b = 0; b < 4; b++) {
                U64F d2; d2.f.x = as4[b]; d2.f.y = as4[b];
                ffma2(acc[0][b], p0.u, d2.u);
                ffma2(acc[1][b], p1.u, d2.u);
            }
        }
    }

    float bias[4];
#pragma unroll
    for (int j = 0; j < 4; j++) bias[j] = bfc[tx + 32 * j];

#pragma unroll
    for (int b = 0; b < 4; b++) {
        float* yp = y + (base + lb0 + b) * DIN + tx;
        U64F u0, u1; u0.u = acc[0][b]; u1.u = acc[1][b];
        yp[0]  = tanhf(u0.f.x + bias[0]);
        yp[32] = tanhf(u0.f.y + bias[1]);
        yp[64] = tanhf(u1.f.x + bias[2]);
        yp[96] = tanhf(u1.f.y + bias[3]);
    }
}

// ---------------------------------------------------------------------------
extern "C" void kernel_launch(void* const* d_in, const int* in_sizes, int n_in,
                              void* d_out, int out_size) {
    const float* x   = (const float*)d_in[0];
    const float* Wih = (const float*)d_in[1];
    const float* Whh = (const float*)d_in[2];
    const float* bih = (const float*)d_in[3];
    const float* bhh = (const float*)d_in[4];
    const float* Wfc = (const float*)d_in[5];
    const float* bfc = (const float*)d_in[6];
    float* y = (float*)d_out;

    cudaFuncSetAttribute(k_pre, cudaFuncAttributeMaxDynamicSharedMemorySize, PRE_SMEM);
    cudaFuncSetAttribute(k_out, cudaFuncAttributeMaxDynamicSharedMemorySize, OUT_SMEM);

    k_xT<<<dim3(L_SEQ / 32, (B_SZ * DIN) / 32), 256>>>(x);
    k_pre<<<128, 512, PRE_SMEM>>>(Wih, bih, bhh);
    k_rnn<<<64, 640>>>(Whh);
    k_out<<<(L_SEQ * B_SZ) / 64, 512, OUT_SMEM>>>(Wfc, bfc, y);
}

// round 17
// speedup vs baseline: 2.1143x; 1.0066x over previous
#include <cuda_runtime.h>
#include <math.h>
#include <stdint.h>

// Problem constants
#define L_SEQ 2048
#define B_SZ  32
#define DIN   128
#define DST   512
#define NB4   4      // batches per rnn cluster

// Scratch (device globals per allocation rules)
__device__ float g_pre[L_SEQ * B_SZ * DST];   // [l][b][h]   128 MB
__device__ float g_hs [L_SEQ * B_SZ * DST];   // [l][b][h]   128 MB
__device__ float g_xT [L_SEQ * B_SZ * DIN];   // [l][b][d]    32 MB

union F4U  { float4 f4; ulonglong2 u2; };
union U64F { unsigned long long u; float2 f; };

__device__ __forceinline__ void ffma2(unsigned long long& acc,
                                      unsigned long long a,
                                      unsigned long long b) {
    asm volatile("fma.rn.f32x2 %0, %1, %2, %0;" : "+l"(acc) : "l"(a), "l"(b));
}

__device__ __forceinline__ uint32_t smem_u32(const void* p) {
    return (uint32_t)__cvta_generic_to_shared(p);
}

// Fast tanh for the recurrent chain: MUFU.EX2-based, ~1e-7 abs error.
__device__ __forceinline__ float ftanh(float x) {
    float e = __expf(2.0f * x);
    return (e - 1.0f) / (e + 1.0f);
}

__device__ __forceinline__ void mbar_wait_cluster(uint32_t addr, uint32_t parity) {
    asm volatile(
        "{\n\t"
        ".reg .pred P;\n\t"
        "WAIT%=:\n\t"
        "mbarrier.try_wait.parity.acquire.cluster.shared::cta.b64 P, [%0], %1, 0x989680;\n\t"
        "@P bra DONE%=;\n\t"
        "bra WAIT%=;\n\t"
        "DONE%=:\n\t"
        "}\n"
        :: "r"(addr), "r"(parity) : "memory");
}

// ---------------------------------------------------------------------------
// Kernel 0: transpose x[b][d][l] -> xT[l][b*128+d].
// ---------------------------------------------------------------------------
__global__ void __launch_bounds__(256) k_xT(const float* __restrict__ x) {
    __shared__ float sm[32 * 33];
    const int l0  = blockIdx.x * 32;
    const int bd0 = blockIdx.y * 32;
    const int t   = threadIdx.x;
    for (int i = t; i < 1024; i += 256) {
        int r = i >> 5, c = i & 31;
        sm[r * 33 + c] = x[(size_t)(bd0 + r) * L_SEQ + l0 + c];
    }
    __syncthreads();
    for (int i = t; i < 1024; i += 256) {
        int r = i >> 5, c = i & 31;
        g_xT[(size_t)(l0 + r) * (B_SZ * DIN) + bd0 + c] = sm[c * 33 + r];
    }
}

// ---------------------------------------------------------------------------
// Kernel 1: pre[l][b][h]. 128 CTAs; each stages its W_ih half ONCE and
// sweeps 32 timesteps (l = bid/2 + 64*i).
// ---------------------------------------------------------------------------
#define PRE_SMEM ((128 * 257 + 128 * 36) * 4)

__global__ void __launch_bounds__(512) k_pre(const float* __restrict__ Wih,
                                             const float* __restrict__ bih,
                                             const float* __restrict__ bhh) {
    extern __shared__ float sm[];
    float* w_s = sm;               // [128 d][257]
    float* x_s = sm + 128 * 257;   // [128 d][36]

    const int hb    = blockIdx.x & 1;
    const int h0    = hb * 256;
    const int lbase = blockIdx.x >> 1;   // 0..63
    const int t     = threadIdx.x;

    for (int idx = t; idx < 256 * 128; idx += 512) {
        int d = idx & 127, hh = idx >> 7;
        w_s[d * 257 + hh] = Wih[(size_t)(h0 + hh) * DIN + d];
    }

    const int tx = t & 63;
    const int b0 = (t >> 6) * 4;

    float bias[4];
#pragma unroll
    for (int j = 0; j < 4; j++)
        bias[j] = bih[h0 + tx + 64 * j] + bhh[h0 + tx + 64 * j];
    __syncthreads();

    for (int i = 0; i < 32; i++) {
        const int l = lbase + 64 * i;
        for (int idx = t; idx < B_SZ * DIN; idx += 512) {
            int d = idx & 127, b = idx >> 7;
            x_s[d * 36 + b] = g_xT[(size_t)l * (B_SZ * DIN) + b * DIN + d];
        }
        __syncthreads();

        unsigned long long acc[2][4];
#pragma unroll
        for (int m = 0; m < 2; m++)
#pragma unroll
            for (int b = 0; b < 4; b++) acc[m][b] = 0ull;

#pragma unroll 4
        for (int k = 0; k < 128; k++) {
            const float* wr = w_s + k * 257 + tx;
            U64F p0, p1;
            p0.f.x = wr[0];   p0.f.y = wr[64];
            p1.f.x = wr[128]; p1.f.y = wr[192];
            F4U xv; xv.f4 = *(const float4*)(x_s + k * 36 + b0);
            float xs[4] = {xv.f4.x, xv.f4.y, xv.f4.z, xv.f4.w};
#pragma unroll
            for (int b = 0; b < 4; b++) {
                U64F d2; d2.f.x = xs[b]; d2.f.y = xs[b];
                ffma2(acc[0][b], p0.u, d2.u);
                ffma2(acc[1][b], p1.u, d2.u);
            }
        }

#pragma unroll
        for (int b = 0; b < 4; b++) {
            float* pr = g_pre + ((size_t)l * B_SZ + b0 + b) * DST + h0 + tx;
            U64F u0, u1; u0.u = acc[0][b]; u1.u = acc[1][b];
            pr[0]   = u0.f.x + bias[0];
            pr[64]  = u0.f.y + bias[1];
            pr[128] = u1.f.x + bias[2];
            pr[192] = u1.f.y + bias[3];
        }
        __syncthreads();     // x_s reusable next iteration
    }
}

// ---------------------------------------------------------------------------
// Kernel 2: recurrent scan — R10 champion machinery, with two chain trims:
//  (a) red transposed to [kslice][row]: conflict-free writes AND reads
//      (tail reduce = 8 contiguous float2 loads instead of 16 conflicted).
//  (b) g_hs store moved after the DSMEM pushes + arrives.
// ---------------------------------------------------------------------------
__global__ void __launch_bounds__(640, 1) __cluster_dims__(8, 1, 1)
k_rnn(const float* __restrict__ Whh) {
    __shared__ float hbuf[2][NB4 * DST];     // 16 KB exchange buffers
    __shared__ float red[2][NB4][8][64];     // 8 KB partials [par][b][kslice][row]
    __shared__ __align__(8) unsigned long long barr[NB4][2][8]; // [b][slot][src]

    const int t    = threadIdx.x;
    const int warp = t >> 5;
    const int lane = t & 31;
    uint32_t rank;
    asm("mov.u32 %0, %%cluster_ctarank;" : "=r"(rank));
    const int cl = blockIdx.x >> 3;          // cluster id 0..7

    // compute-warp constants + register W
    const int rg  = warp & 1;
    const int kw  = warp >> 1;               // K slice / source CTA 0..7
    const int row = rg * 32 + lane;          // local row 0..63
    const int ks  = kw * 64;
    F4U w[16];
    if (t < 512) {
        const float4* wp = (const float4*)(Whh + (size_t)(rank * 64 + row) * DST + ks);
#pragma unroll
        for (int i = 0; i < 16; i++) w[i].f4 = wp[i];
    }

    // h_{-1} = 0 lives in parity buffer 1
    for (int i = t; i < NB4 * DST; i += 640) hbuf[1][i] = 0.f;

    uint32_t bar0 = smem_u32(&barr[0][0][0]);
    if (t == 0) {
        for (int i = 0; i < NB4 * 2 * 8; i++)
            asm volatile("mbarrier.init.shared.b64 [%0], %1;"
                         :: "r"(bar0 + 8u * i), "r"(1u) : "memory");
        asm volatile("fence.mbarrier_init.release.cluster;" ::: "memory");
    }
    __syncthreads();
    asm volatile("barrier.cluster.arrive.aligned;" ::: "memory");
    asm volatile("barrier.cluster.wait.aligned;" ::: "memory");

    const uint32_t hbase = smem_u32(&hbuf[0][0]);
    uint32_t peer_h[8];
#pragma unroll
    for (int p = 0; p < 8; p++)
        asm("mapa.shared::cluster.u32 %0, %1, %2;" : "=r"(peer_h[p]) : "r"(hbase), "r"(p));

    if (t < 512) {
        // ================= COMPUTE WARPS =================
        for (int l = 0; l < L_SEQ; l++) {
            const int prev = (l & 1) ^ 1;
            const int rbuf = l & 1;
            const uint32_t wslot = (uint32_t)((l - 1) & 1);
            const uint32_t wpar  = (uint32_t)(((l - 1) >> 1) & 1);
            const float* hbp = hbuf[prev];
            const uint32_t srcoff = 8u * (wslot * 8u + (uint32_t)kw);

#pragma unroll
            for (int b = 0; b < NB4; b++) {
                if (l > 0)
                    mbar_wait_cluster(bar0 + (uint32_t)(b * 128) + srcoff, wpar);
                const float4* hp = (const float4*)(hbp + b * DST + ks);
                unsigned long long a0 = 0ull, a1 = 0ull;
#pragma unroll
                for (int i = 0; i < 16; i++) {
                    F4U hv; hv.f4 = hp[i];      // broadcast LDS
                    ffma2(a0, hv.u2.x, w[i].u2.x);
                    ffma2(a1, hv.u2.y, w[i].u2.y);
                }
                U64F u0, u1; u0.u = a0; u1.u = a1;
                // conflict-free: fixed kw, lanes write contiguous rows
                red[rbuf][b][kw][row] = u0.f.x + u0.f.y + u1.f.x + u1.f.y;
                asm volatile("bar.arrive %0, 544;"
                             :: "r"(1 + b * 2 + (l & 1)) : "memory");
            }
        }
    } else {
        // ================= TAIL WARPS (one per batch) =================
        const int tb = warp - 16;               // my batch 0..3
        const int u  = lane;                    // rows 2u, 2u+1 (contiguous)
        const size_t oi0 = (size_t)(cl * NB4 + tb) * DST + rank * 64 + 2 * u;
        const uint32_t po0 = (uint32_t)((tb * DST + (int)rank * 64 + 2 * u) * 4);

        for (int l = 0; l < L_SEQ; l++) {
            const int cur  = l & 1;
            const int rbuf = l & 1;
            float2 pv = *(const float2*)(g_pre + (size_t)l * (B_SZ * DST) + oi0);

            asm volatile("bar.sync %0, 544;"
                         :: "r"(1 + tb * 2 + (l & 1)) : "memory");

            float s0 = pv.x, s1 = pv.y;
#pragma unroll
            for (int k2 = 0; k2 < 8; k2++) {
                float2 v = *(const float2*)&red[rbuf][tb][k2][2 * u];  // conflict-free
                s0 += v.x; s1 += v.y;
            }
            U64F hv2; hv2.f.x = ftanh(s0); hv2.f.y = ftanh(s1);

            if (l < L_SEQ - 1) {
                uint32_t off0 = (uint32_t)(cur * NB4 * DST * 4) + po0;
#pragma unroll
                for (int p = 0; p < 8; p++)
                    asm volatile("st.shared::cluster.u64 [%0], %1;"
                                 :: "r"(peer_h[p] + off0), "l"(hv2.u) : "memory");
                __syncwarp();   // order this warp's pushes before the arrives
                if (u < 8) {
                    uint32_t local = bar0 + (uint32_t)(tb * 128)
                                   + 8u * ((uint32_t)cur * 8u + rank);
                    uint32_t ra;
                    asm("mapa.shared::cluster.u32 %0, %1, %2;"
                        : "=r"(ra) : "r"(local), "r"(u));
                    asm volatile("mbarrier.arrive.release.cluster.shared::cluster.b64 _, [%0];"
                                 :: "r"(ra) : "memory");
                }
            }
            // global store off the critical chain (after the arrives)
            *(float2*)(g_hs + (size_t)l * (B_SZ * DST) + oi0) = hv2.f;
        }
    }

    // No CTA may exit while peers could still touch its smem.
    asm volatile("barrier.cluster.arrive.aligned;" ::: "memory");
    asm volatile("barrier.cluster.wait.aligned;" ::: "memory");
}

// ---------------------------------------------------------------------------
// Kernel 3: y[lb][o] = tanh(b_fc[o] + sum_k hs[lb][k] * W_fc[o][k])
// ---------------------------------------------------------------------------
#define OUT_SMEM ((128 * 132 + 128 * 68) * 4)

__global__ void __launch_bounds__(512) k_out(const float* __restrict__ Wfc,
                                             const float* __restrict__ bfc,
                                             float* __restrict__ y) {
    extern __shared__ float sm[];
    float* w_s = sm;               // [128 kk][132]
    float* a_s = sm + 128 * 132;   // [128 kk][68]

    const int t = threadIdx.x;
    const size_t base = (size_t)blockIdx.x * 64;
    const int tx  = t & 31;
    const int lb0 = (t >> 5) * 4;

    unsigned long long acc[2][4];
#pragma unroll
    for (int m = 0; m < 2; m++)
#pragma unroll
        for (int b = 0; b < 4; b++) acc[m][b] = 0ull;

    for (int kc = 0; kc < 4; kc++) {
        __syncthreads();
        for (int idx = t; idx < 128 * 128; idx += 512) {
            int kk = idx & 127, o = idx >> 7;
            w_s[kk * 132 + o] = Wfc[(size_t)o * DST + kc * 128 + kk];
        }
        for (int idx = t; idx < 64 * 128; idx += 512) {
            int kk = idx & 127, row = idx >> 7;
            a_s[kk * 68 + row] = g_hs[(base + row) * DST + kc * 128 + kk];
        }
        __syncthreads();

#pragma unroll 4
        for (int k = 0; k < 128; k++) {
            const float* wr = w_s + k * 132 + tx;
            U64F p0, p1;
            p0.f.x = wr[0];  p0.f.y = wr[32];
            p1.f.x = wr[64]; p1.f.y = wr[96];
            F4U av; av.f4 = *(const float4*)(a_s + k * 68 + lb0);
            float as4[4] = {av.f4.x, av.f4.y, av.f4.z, av.f4.w};
#pragma unroll
            for (int b = 0; b < 4; b++) {
                U64F d2; d2.f.x = as4[b]; d2.f.y = as4[b];
                ffma2(acc[0][b], p0.u, d2.u);
                ffma2(acc[1][b], p1.u, d2.u);
            }
        }
    }

    float bias[4];
#pragma unroll
    for (int j = 0; j < 4; j++) bias[j] = bfc[tx + 32 * j];

#pragma unroll
    for (int b = 0; b < 4; b++) {
        float* yp = y + (base + lb0 + b) * DIN + tx;
        U64F u0, u1; u0.u = acc[0][b]; u1.u = acc[1][b];
        yp[0]  = tanhf(u0.f.x + bias[0]);
        yp[32] = tanhf(u0.f.y + bias[1]);
        yp[64] = tanhf(u1.f.x + bias[2]);
        yp[96] = tanhf(u1.f.y + bias[3]);
    }
}

// ---------------------------------------------------------------------------
extern "C" void kernel_launch(void* const* d_in, const int* in_sizes, int n_in,
                              void* d_out, int out_size) {
    const float* x   = (const float*)d_in[0];
    const float* Wih = (const float*)d_in[1];
    const float* Whh = (const float*)d_in[2];
    const float* bih = (const float*)d_in[3];
    const float* bhh = (const float*)d_in[4];
    const float* Wfc = (const float*)d_in[5];
    const float* bfc = (const float*)d_in[6];
    float* y = (float*)d_out;

    cudaFuncSetAttribute(k_pre, cudaFuncAttributeMaxDynamicSharedMemorySize, PRE_SMEM);
    cudaFuncSetAttribute(k_out, cudaFuncAttributeMaxDynamicSharedMemorySize, OUT_SMEM);

    k_xT<<<dim3(L_SEQ / 32, (B_SZ * DIN) / 32), 256>>>(x);
    k_pre<<<128, 512, PRE_SMEM>>>(Wih, bih, bhh);
    k_rnn<<<64, 640>>>(Whh);
    k_out<<<(L_SEQ * B_SZ) / 64, 512, OUT_SMEM>>>(Wfc, bfc, y);
}